// round 9
// baseline (speedup 1.0000x reference)
#include <cuda_runtime.h>
#include <cuda_bf16.h>
#include <cstdint>

#define NN 100000
#define EE 1600000
#define DD 128
#define LN_EPS 1e-5f
#define SCAN_BLK 1024
#define NB ((NN + SCAN_BLK - 1) / SCAN_BLK)   // 98

// ---------------- scratch (no allocs allowed) ----------------
__device__ float g_h[(size_t)NN * DD];    // layer-0 output
__device__ float g_h2[(size_t)NN * DD];   // layer-1 output (double buffer)
__device__ float g_agg[(size_t)NN * DD];  // per-block mean-aggregated feats
__device__ int   g_rowptr[NN + 1];
__device__ int   g_cursor[NN];            // deg counter, then fill cursor
__device__ int   g_col[EE];
__device__ int   g_blocksum[128];
__device__ int   g_is64;                  // edge_index dtype flag

// ---------------- init: zero cursor everywhere; block 0 detects dtype ------
__global__ __launch_bounds__(256) void k_init(const unsigned* __restrict__ w) {
    int i = blockIdx.x * blockDim.x + threadIdx.x;
    if (i < NN) g_cursor[i] = 0;
    if (blockIdx.x == 0) {
        __shared__ unsigned s[256];
        int tid = threadIdx.x;
        unsigned v = 0;
#pragma unroll
        for (int k = 0; k < 8; k++) v |= w[2 * (tid + 256 * k) + 1];
        s[tid] = v;
        __syncthreads();
        for (int off = 128; off > 0; off >>= 1) {
            if (tid < off) s[tid] |= s[tid + off];
            __syncthreads();
        }
        if (tid == 0) g_is64 = (s[0] == 0u) ? 1 : 0;
    }
}

__device__ __forceinline__ int edge_at(const void* ei, size_t idx) {
    int v;
    if (g_is64) v = (int)((const long long*)ei)[idx];
    else        v = ((const int*)ei)[idx];
    v = (v < 0) ? 0 : (v >= NN ? NN - 1 : v);
    return v;
}

// ---------------- CSR build ----------------
__global__ void k_deg_count(const void* __restrict__ ei) {
    int e = blockIdx.x * blockDim.x + threadIdx.x;
    if (e < EE) atomicAdd(&g_cursor[edge_at(ei, (size_t)EE + e)], 1);
}

__global__ __launch_bounds__(SCAN_BLK) void k_scan_block() {
    __shared__ int s[SCAN_BLK];
    int tid = threadIdx.x;
    int i = blockIdx.x * SCAN_BLK + tid;
    int v = (i < NN) ? g_cursor[i] : 0;
    s[tid] = v;
    __syncthreads();
#pragma unroll
    for (int off = 1; off < SCAN_BLK; off <<= 1) {
        int t = (tid >= off) ? s[tid - off] : 0;
        __syncthreads();
        s[tid] += t;
        __syncthreads();
    }
    if (i < NN) g_rowptr[i + 1] = s[tid];
    if (tid == SCAN_BLK - 1) g_blocksum[blockIdx.x] = s[tid];
}

// finalize with inline block-prefix (block-uniform -> thread 0 computes it)
__global__ __launch_bounds__(256) void k_scan_finalize() {
    __shared__ int pre_s;
    int i = blockIdx.x * 256 + threadIdx.x;
    if (threadIdx.x == 0) {
        int b = blockIdx.x >> 2;
        int run = 0;
        for (int j = 0; j < b; j++) run += g_blocksum[j];
        pre_s = run;
    }
    __syncthreads();
    if (i >= NN) return;
    g_rowptr[i + 1] += pre_s;
    if (i == 0) g_rowptr[0] = 0;
    g_cursor[i] = 0;
}

__global__ void k_fill(const void* __restrict__ ei) {
    int e = blockIdx.x * blockDim.x + threadIdx.x;
    if (e >= EE) return;
    int dst = edge_at(ei, (size_t)EE + e);
    int src = edge_at(ei, (size_t)e);
    int pos = g_rowptr[dst] + atomicAdd(&g_cursor[dst], 1);
    g_col[pos] = src;
}

// ---------------- tf32 tensor-core GEMM machinery ----------------
__device__ __forceinline__ unsigned f2tf32(float f) {
    unsigned u;
    asm("cvt.rna.tf32.f32 %0, %1;" : "=r"(u) : "f"(f));
    return u;
}

__device__ __forceinline__ void mma_tf32(float* d, const unsigned* a,
                                         const unsigned* b) {
    asm volatile(
        "mma.sync.aligned.m16n8k8.row.col.f32.tf32.tf32.f32 "
        "{%0,%1,%2,%3}, {%4,%5,%6,%7}, {%8,%9}, {%0,%1,%2,%3};"
        : "+f"(d[0]), "+f"(d[1]), "+f"(d[2]), "+f"(d[3])
        : "r"(a[0]), "r"(a[1]), "r"(a[2]), "r"(a[3]), "r"(b[0]), "r"(b[1]));
}

#define LDK 36  // padded smem row: bank-conflict-free fragments, 16B-aligned quads

// ---- fused SAGE layer: gather + GEMM + bias + LN + SiLU in one kernel ----
// phase 1: block mean-aggregates its own 128 rows into g_agg (block-local)
// phase 2: h_out = SiLU(LN([g_agg | h_in] @ [Wl|Wr]^T + b))
// 2 CTAs/SM: CTA A's gather overlaps CTA B's MMAs.
__global__ __launch_bounds__(256, 2) void k_layer_tc(
    const float* __restrict__ hin, float* __restrict__ hout,
    const float* __restrict__ Wl, const float* __restrict__ bl,
    const float* __restrict__ Wr, const float* __restrict__ br,
    const float* __restrict__ lng, const float* __restrict__ lnb) {
    __shared__ unsigned As_[128 * LDK];
    __shared__ unsigned Bs_[128 * LDK];
    __shared__ float red_s[128][2][2];
    __shared__ float bias_s[128], lng_s[128], lnb_s[128];

    const int tid = threadIdx.x;
    const int block_m = blockIdx.x * 128;
    const int wid = tid >> 5, lane = tid & 31;

    if (tid < 128) {
        bias_s[tid] = bl[tid] + br[tid];
        lng_s[tid] = lng[tid];
        lnb_s[tid] = lnb[tid];
    }

    // ---- phase 1: aggregate this block's rows (warp per row, 16 rows/warp) ----
    for (int r = wid; r < 128; r += 8) {
        int node = block_m + r;
        if (node >= NN) break;  // warp-uniform
        int start = g_rowptr[node];
        int end = g_rowptr[node + 1];
        float4 a0 = make_float4(0.f, 0.f, 0.f, 0.f);
        float4 a1 = make_float4(0.f, 0.f, 0.f, 0.f);
        int j = start;
        for (; j + 4 <= end; j += 4) {
            int s0 = g_col[j], s1 = g_col[j + 1], s2 = g_col[j + 2], s3 = g_col[j + 3];
            float4 v0 = ((const float4*)(hin + (size_t)s0 * DD))[lane];
            float4 v1 = ((const float4*)(hin + (size_t)s1 * DD))[lane];
            float4 v2 = ((const float4*)(hin + (size_t)s2 * DD))[lane];
            float4 v3 = ((const float4*)(hin + (size_t)s3 * DD))[lane];
            a0.x += v0.x; a0.y += v0.y; a0.z += v0.z; a0.w += v0.w;
            a1.x += v1.x; a1.y += v1.y; a1.z += v1.z; a1.w += v1.w;
            a0.x += v2.x; a0.y += v2.y; a0.z += v2.z; a0.w += v2.w;
            a1.x += v3.x; a1.y += v3.y; a1.z += v3.z; a1.w += v3.w;
        }
        for (; j < end; j++) {
            float4 v = ((const float4*)(hin + (size_t)g_col[j] * DD))[lane];
            a0.x += v.x; a0.y += v.y; a0.z += v.z; a0.w += v.w;
        }
        float inv = (end > start) ? (1.0f / (float)(end - start)) : 0.0f;
        float4 rr;
        rr.x = (a0.x + a1.x) * inv; rr.y = (a0.y + a1.y) * inv;
        rr.z = (a0.z + a1.z) * inv; rr.w = (a0.w + a1.w) * inv;
        ((float4*)(g_agg + (size_t)node * DD))[lane] = rr;
    }
    __syncthreads();  // agg visible block-wide (only this block reads these rows)

    // ---- phase 2: GEMM ----
    const int wm = wid >> 1, wn = wid & 1;
    const int g = lane >> 2, c = lane & 3;
    const int m_w = 32 * wm, n_w = 64 * wn;

    float d[2][8][4];
#pragma unroll
    for (int mt = 0; mt < 2; mt++)
#pragma unroll
        for (int nt = 0; nt < 8; nt++)
#pragma unroll
            for (int r = 0; r < 4; r++) d[mt][nt][r] = 0.f;

    for (int k0 = 0; k0 < 2 * DD; k0 += 32) {
        const float* Wsrc = (k0 < DD) ? Wl : Wr;
        const int kw0 = k0 & (DD - 1);
#pragma unroll
        for (int i = 0; i < 4; i++) {
            int idx = tid + 256 * i;
            int row = idx >> 3;
            int kq = (idx & 7) * 4;
            int gm = block_m + row;
            float4 av = make_float4(0.f, 0.f, 0.f, 0.f);
            if (gm < NN) {
                int k = k0 + kq;
                if (k < DD) av = *(const float4*)(&g_agg[(size_t)gm * DD + k]);
                else        av = *(const float4*)(hin + (size_t)gm * DD + (k - DD));
            }
            *(uint4*)&As_[row * LDK + kq] =
                make_uint4(f2tf32(av.x), f2tf32(av.y), f2tf32(av.z), f2tf32(av.w));

            float4 wv = *(const float4*)(Wsrc + row * DD + kw0 + kq);
            *(uint4*)&Bs_[row * LDK + kq] =
                make_uint4(f2tf32(wv.x), f2tf32(wv.y), f2tf32(wv.z), f2tf32(wv.w));
        }
        __syncthreads();

#pragma unroll
        for (int ks = 0; ks < 4; ks++) {
            const int kk = ks * 8;
            unsigned a[2][4];
#pragma unroll
            for (int mt = 0; mt < 2; mt++) {
                int mr = m_w + 16 * mt + g;
                a[mt][0] = As_[mr * LDK + kk + c];
                a[mt][1] = As_[(mr + 8) * LDK + kk + c];
                a[mt][2] = As_[mr * LDK + kk + c + 4];
                a[mt][3] = As_[(mr + 8) * LDK + kk + c + 4];
            }
            unsigned bf[8][2];
#pragma unroll
            for (int nt = 0; nt < 8; nt++) {
                int n = n_w + 8 * nt + g;
                bf[nt][0] = Bs_[n * LDK + kk + c];
                bf[nt][1] = Bs_[n * LDK + kk + c + 4];
            }
#pragma unroll
            for (int mt = 0; mt < 2; mt++)
#pragma unroll
                for (int nt = 0; nt < 8; nt++)
                    mma_tf32(d[mt][nt], a[mt], bf[nt]);
        }
        __syncthreads();
    }

    // ---- epilogue: bias, LN (shuffle + cross-warp smem), SiLU, store ----
#pragma unroll
    for (int mt = 0; mt < 2; mt++) {
        float s0 = 0.f, q0 = 0.f, s1 = 0.f, q1 = 0.f;
#pragma unroll
        for (int nt = 0; nt < 8; nt++) {
            int col = n_w + 8 * nt + 2 * c;
            float b0 = bias_s[col], b1 = bias_s[col + 1];
            float v0 = d[mt][nt][0] + b0, v1 = d[mt][nt][1] + b1;
            float v2 = d[mt][nt][2] + b0, v3 = d[mt][nt][3] + b1;
            d[mt][nt][0] = v0; d[mt][nt][1] = v1;
            d[mt][nt][2] = v2; d[mt][nt][3] = v3;
            s0 += v0 + v1; q0 += v0 * v0 + v1 * v1;
            s1 += v2 + v3; q1 += v2 * v2 + v3 * v3;
        }
#pragma unroll
        for (int off = 1; off <= 2; off <<= 1) {
            s0 += __shfl_xor_sync(0xffffffffu, s0, off);
            q0 += __shfl_xor_sync(0xffffffffu, q0, off);
            s1 += __shfl_xor_sync(0xffffffffu, s1, off);
            q1 += __shfl_xor_sync(0xffffffffu, q1, off);
        }
        if (c == 0) {
            int r0 = m_w + 16 * mt + g;
            red_s[r0][wn][0] = s0; red_s[r0][wn][1] = q0;
            red_s[r0 + 8][wn][0] = s1; red_s[r0 + 8][wn][1] = q1;
        }
    }
    __syncthreads();

#pragma unroll
    for (int mt = 0; mt < 2; mt++) {
        int r0 = m_w + 16 * mt + g;
        int r1 = r0 + 8;
        float sum0 = red_s[r0][0][0] + red_s[r0][1][0];
        float ssq0 = red_s[r0][0][1] + red_s[r0][1][1];
        float sum1 = red_s[r1][0][0] + red_s[r1][1][0];
        float ssq1 = red_s[r1][0][1] + red_s[r1][1][1];
        float mu0 = sum0 * (1.0f / DD);
        float rs0 = rsqrtf(ssq0 * (1.0f / DD) - mu0 * mu0 + LN_EPS);
        float mu1 = sum1 * (1.0f / DD);
        float rs1 = rsqrtf(ssq1 * (1.0f / DD) - mu1 * mu1 + LN_EPS);
        int gm0 = block_m + r0, gm1 = block_m + r1;
#pragma unroll
        for (int nt = 0; nt < 8; nt++) {
            int col = n_w + 8 * nt + 2 * c;
            float gg0 = lng_s[col], gg1 = lng_s[col + 1];
            float bb0 = lnb_s[col], bb1 = lnb_s[col + 1];
            if (gm0 < NN) {
                float y0 = (d[mt][nt][0] - mu0) * rs0 * gg0 + bb0;
                float y1 = (d[mt][nt][1] - mu0) * rs0 * gg1 + bb1;
                y0 = y0 / (1.f + __expf(-y0));
                y1 = y1 / (1.f + __expf(-y1));
                *(float2*)&hout[(size_t)gm0 * DD + col] = make_float2(y0, y1);
            }
            if (gm1 < NN) {
                float y2 = (d[mt][nt][2] - mu1) * rs1 * gg0 + bb0;
                float y3 = (d[mt][nt][3] - mu1) * rs1 * gg1 + bb1;
                y2 = y2 / (1.f + __expf(-y2));
                y3 = y3 / (1.f + __expf(-y3));
                *(float2*)&hout[(size_t)gm1 * DD + col] = make_float2(y2, y3);
            }
        }
    }
}

// ---- fused MLP head: out = relu(hin @ W1^T + b1) @ w2 + b2 ----
__global__ __launch_bounds__(256, 2) void k_mlp_fused(const float* __restrict__ hin,
                                                      const float* __restrict__ W1,
                                                      const float* __restrict__ b1,
                                                      const float* __restrict__ w2,
                                                      const float* __restrict__ b2,
                                                      float* __restrict__ out) {
    __shared__ unsigned As_[128 * LDK];
    __shared__ unsigned Bs_[128 * LDK];
    __shared__ float red_s[128][2];
    __shared__ float bias_s[128], w2_s[128];

    const int tid = threadIdx.x;
    const int block_m = blockIdx.x * 128;
    if (tid < 128) {
        bias_s[tid] = b1[tid];
        w2_s[tid] = w2[tid];
    }

    const int wid = tid >> 5, lane = tid & 31;
    const int wm = wid >> 1, wn = wid & 1;
    const int g = lane >> 2, c = lane & 3;
    const int m_w = 32 * wm, n_w = 64 * wn;

    float d[2][8][4];
#pragma unroll
    for (int mt = 0; mt < 2; mt++)
#pragma unroll
        for (int nt = 0; nt < 8; nt++)
#pragma unroll
            for (int r = 0; r < 4; r++) d[mt][nt][r] = 0.f;

    for (int k0 = 0; k0 < DD; k0 += 32) {
#pragma unroll
        for (int i = 0; i < 4; i++) {
            int idx = tid + 256 * i;
            int row = idx >> 3;
            int kq = (idx & 7) * 4;
            int gm = block_m + row;
            float4 av = make_float4(0.f, 0.f, 0.f, 0.f);
            if (gm < NN) av = *(const float4*)(hin + (size_t)gm * DD + k0 + kq);
            *(uint4*)&As_[row * LDK + kq] =
                make_uint4(f2tf32(av.x), f2tf32(av.y), f2tf32(av.z), f2tf32(av.w));

            float4 wv = *(const float4*)(W1 + row * DD + k0 + kq);
            *(uint4*)&Bs_[row * LDK + kq] =
                make_uint4(f2tf32(wv.x), f2tf32(wv.y), f2tf32(wv.z), f2tf32(wv.w));
        }
        __syncthreads();

#pragma unroll
        for (int ks = 0; ks < 4; ks++) {
            const int kk = ks * 8;
            unsigned a[2][4];
#pragma unroll
            for (int mt = 0; mt < 2; mt++) {
                int mr = m_w + 16 * mt + g;
                a[mt][0] = As_[mr * LDK + kk + c];
                a[mt][1] = As_[(mr + 8) * LDK + kk + c];
                a[mt][2] = As_[mr * LDK + kk + c + 4];
                a[mt][3] = As_[(mr + 8) * LDK + kk + c + 4];
            }
            unsigned bf[8][2];
#pragma unroll
            for (int nt = 0; nt < 8; nt++) {
                int n = n_w + 8 * nt + g;
                bf[nt][0] = Bs_[n * LDK + kk + c];
                bf[nt][1] = Bs_[n * LDK + kk + c + 4];
            }
#pragma unroll
            for (int mt = 0; mt < 2; mt++)
#pragma unroll
                for (int nt = 0; nt < 8; nt++)
                    mma_tf32(d[mt][nt], a[mt], bf[nt]);
        }
        __syncthreads();
    }

#pragma unroll
    for (int mt = 0; mt < 2; mt++) {
        float p0 = 0.f, p1 = 0.f;
#pragma unroll
        for (int nt = 0; nt < 8; nt++) {
            int col = n_w + 8 * nt + 2 * c;
            float b0 = bias_s[col], b1v = bias_s[col + 1];
            float w0 = w2_s[col], w1 = w2_s[col + 1];
            p0 += fmaxf(d[mt][nt][0] + b0, 0.f) * w0
                + fmaxf(d[mt][nt][1] + b1v, 0.f) * w1;
            p1 += fmaxf(d[mt][nt][2] + b0, 0.f) * w0
                + fmaxf(d[mt][nt][3] + b1v, 0.f) * w1;
        }
#pragma unroll
        for (int off = 1; off <= 2; off <<= 1) {
            p0 += __shfl_xor_sync(0xffffffffu, p0, off);
            p1 += __shfl_xor_sync(0xffffffffu, p1, off);
        }
        if (c == 0) {
            int r0 = m_w + 16 * mt + g;
            red_s[r0][wn] = p0;
            red_s[r0 + 8][wn] = p1;
        }
    }
    __syncthreads();
    if (tid < 128) {
        int gm = block_m + tid;
        if (gm < NN) out[gm] = red_s[tid][0] + red_s[tid][1] + b2[0];
    }
}

// ---------------- launch ----------------
extern "C" void kernel_launch(void* const* d_in, const int* in_sizes, int n_in,
                              void* d_out, int out_size) {
    const float* x = (const float*)d_in[0];
    const void* ei = d_in[1];
    const float* lin_l_w = (const float*)d_in[2];
    const float* lin_l_b = (const float*)d_in[3];
    const float* lin_r_w = (const float*)d_in[4];
    const float* lin_r_b = (const float*)d_in[5];
    const float* ln_g = (const float*)d_in[6];
    const float* ln_b = (const float*)d_in[7];
    const float* mlp_w1 = (const float*)d_in[8];
    const float* mlp_b1 = (const float*)d_in[9];
    const float* mlp_w2 = (const float*)d_in[10];
    const float* mlp_b2 = (const float*)d_in[11];
    float* out = (float*)d_out;

    float *p_h, *p_h2;
    cudaGetSymbolAddress((void**)&p_h, g_h);
    cudaGetSymbolAddress((void**)&p_h2, g_h2);

    const int T = 256;
    const int gemm_grid = (NN + 127) / 128;          // 782

    // ---- dtype detect + CSR build ----
    k_init<<<(NN + T - 1) / T, T>>>((const unsigned*)ei);
    k_deg_count<<<(EE + T - 1) / T, T>>>(ei);
    k_scan_block<<<NB, SCAN_BLK>>>();
    k_scan_finalize<<<(NN + T - 1) / T, T>>>();
    k_fill<<<(EE + T - 1) / T, T>>>(ei);

    // ---- layer 0: gather x -> out g_h ----
    k_layer_tc<<<gemm_grid, T>>>(x, p_h, lin_l_w, lin_l_b, lin_r_w, lin_r_b,
                                 ln_g, ln_b);

    // ---- layer 1: gather g_h -> out g_h2 (double buffer, no race) ----
    k_layer_tc<<<gemm_grid, T>>>(p_h, p_h2,
                                 lin_l_w + DD * DD, lin_l_b + DD,
                                 lin_r_w + DD * DD, lin_r_b + DD,
                                 ln_g + DD, ln_b + DD);

    // ---- fused MLP head ----
    k_mlp_fused<<<gemm_grid, T>>>(p_h2, mlp_w1, mlp_b1, mlp_w2, mlp_b2, out);
}

// round 10
// speedup vs baseline: 1.1361x; 1.1361x over previous
#include <cuda_runtime.h>
#include <cuda_bf16.h>
#include <cstdint>

#define NN 100000
#define EE 1600000
#define DD 128
#define LN_EPS 1e-5f
#define SCAN_BLK 1024
#define NB ((NN + SCAN_BLK - 1) / SCAN_BLK)   // 98
#define NCHUNK 4

// ---------------- scratch (no allocs allowed) ----------------
__device__ float g_h[(size_t)NN * DD];    // layer-0 output
__device__ float g_h2[(size_t)NN * DD];   // layer-1 output (double buffer)
__device__ float g_agg[(size_t)NN * DD];  // mean-aggregated feats
__device__ int   g_rowptr[NN + 1];
__device__ int   g_cursor[NN];            // deg counter, then fill cursor
__device__ int   g_col[EE];
__device__ int   g_blocksum[128];
__device__ int   g_is64;                  // edge_index dtype flag

// ---------------- init: zero cursor everywhere; block 0 detects dtype ------
__global__ __launch_bounds__(256) void k_init(const unsigned* __restrict__ w) {
    int i = blockIdx.x * blockDim.x + threadIdx.x;
    if (i < NN) g_cursor[i] = 0;
    if (blockIdx.x == 0) {
        __shared__ unsigned s[256];
        int tid = threadIdx.x;
        unsigned v = 0;
#pragma unroll
        for (int k = 0; k < 8; k++) v |= w[2 * (tid + 256 * k) + 1];
        s[tid] = v;
        __syncthreads();
        for (int off = 128; off > 0; off >>= 1) {
            if (tid < off) s[tid] |= s[tid + off];
            __syncthreads();
        }
        if (tid == 0) g_is64 = (s[0] == 0u) ? 1 : 0;
    }
}

__device__ __forceinline__ int edge_at(const void* ei, size_t idx) {
    int v;
    if (g_is64) v = (int)((const long long*)ei)[idx];
    else        v = ((const int*)ei)[idx];
    v = (v < 0) ? 0 : (v >= NN ? NN - 1 : v);
    return v;
}

// ---------------- CSR build ----------------
__global__ void k_deg_count(const void* __restrict__ ei) {
    int e = blockIdx.x * blockDim.x + threadIdx.x;
    if (e < EE) atomicAdd(&g_cursor[edge_at(ei, (size_t)EE + e)], 1);
}

__global__ __launch_bounds__(SCAN_BLK) void k_scan_block() {
    __shared__ int s[SCAN_BLK];
    int tid = threadIdx.x;
    int i = blockIdx.x * SCAN_BLK + tid;
    int v = (i < NN) ? g_cursor[i] : 0;
    s[tid] = v;
    __syncthreads();
#pragma unroll
    for (int off = 1; off < SCAN_BLK; off <<= 1) {
        int t = (tid >= off) ? s[tid - off] : 0;
        __syncthreads();
        s[tid] += t;
        __syncthreads();
    }
    if (i < NN) g_rowptr[i + 1] = s[tid];
    if (tid == SCAN_BLK - 1) g_blocksum[blockIdx.x] = s[tid];
}

__global__ __launch_bounds__(256) void k_scan_finalize() {
    __shared__ int pre_s;
    int i = blockIdx.x * 256 + threadIdx.x;
    if (threadIdx.x == 0) {
        int b = blockIdx.x >> 2;
        int run = 0;
        for (int j = 0; j < b; j++) run += g_blocksum[j];
        pre_s = run;
    }
    __syncthreads();
    if (i >= NN) return;
    g_rowptr[i + 1] += pre_s;
    if (i == 0) g_rowptr[0] = 0;
    g_cursor[i] = 0;
}

__global__ void k_fill(const void* __restrict__ ei) {
    int e = blockIdx.x * blockDim.x + threadIdx.x;
    if (e >= EE) return;
    int dst = edge_at(ei, (size_t)EE + e);
    int src = edge_at(ei, (size_t)e);
    int pos = g_rowptr[dst] + atomicAdd(&g_cursor[dst], 1);
    g_col[pos] = src;
}

// ---------------- pull-mode mean aggregation (warp per node, chunked) ------
__global__ __launch_bounds__(256) void k_aggregate(const float* __restrict__ hin,
                                                   int base, int count) {
    int w = (blockIdx.x * blockDim.x + threadIdx.x) >> 5;
    int lane = threadIdx.x & 31;
    if (w >= count) return;
    int node = base + w;
    int start = g_rowptr[node];
    int end = g_rowptr[node + 1];
    float4 a0 = make_float4(0.f, 0.f, 0.f, 0.f);
    float4 a1 = make_float4(0.f, 0.f, 0.f, 0.f);
    int j = start;
    for (; j + 4 <= end; j += 4) {
        int s0 = g_col[j], s1 = g_col[j + 1], s2 = g_col[j + 2], s3 = g_col[j + 3];
        float4 v0 = ((const float4*)(hin + (size_t)s0 * DD))[lane];
        float4 v1 = ((const float4*)(hin + (size_t)s1 * DD))[lane];
        float4 v2 = ((const float4*)(hin + (size_t)s2 * DD))[lane];
        float4 v3 = ((const float4*)(hin + (size_t)s3 * DD))[lane];
        a0.x += v0.x; a0.y += v0.y; a0.z += v0.z; a0.w += v0.w;
        a1.x += v1.x; a1.y += v1.y; a1.z += v1.z; a1.w += v1.w;
        a0.x += v2.x; a0.y += v2.y; a0.z += v2.z; a0.w += v2.w;
        a1.x += v3.x; a1.y += v3.y; a1.z += v3.z; a1.w += v3.w;
    }
    for (; j < end; j++) {
        float4 v = ((const float4*)(hin + (size_t)g_col[j] * DD))[lane];
        a0.x += v.x; a0.y += v.y; a0.z += v.z; a0.w += v.w;
    }
    float inv = (end > start) ? (1.0f / (float)(end - start)) : 0.0f;
    float4 r;
    r.x = (a0.x + a1.x) * inv; r.y = (a0.y + a1.y) * inv;
    r.z = (a0.z + a1.z) * inv; r.w = (a0.w + a1.w) * inv;
    ((float4*)(g_agg + (size_t)node * DD))[lane] = r;
}

// ---------------- tf32 tensor-core GEMM machinery ----------------
__device__ __forceinline__ unsigned f2tf32(float f) {
    unsigned u;
    asm("cvt.rna.tf32.f32 %0, %1;" : "=r"(u) : "f"(f));
    return u;
}

__device__ __forceinline__ void mma_tf32(float* d, const unsigned* a,
                                         const unsigned* b) {
    asm volatile(
        "mma.sync.aligned.m16n8k8.row.col.f32.tf32.tf32.f32 "
        "{%0,%1,%2,%3}, {%4,%5,%6,%7}, {%8,%9}, {%0,%1,%2,%3};"
        : "+f"(d[0]), "+f"(d[1]), "+f"(d[2]), "+f"(d[3])
        : "r"(a[0]), "r"(a[1]), "r"(a[2]), "r"(a[3]), "r"(b[0]), "r"(b[1]));
}

#define LDK 36

// ---- fused SAGE layer (chunked): hout = SiLU(LN([agg|hin] @ [Wl|Wr]^T+b)) --
__global__ __launch_bounds__(256, 2) void k_layer_tc(
    const float* __restrict__ hin, float* __restrict__ hout, int m_base,
    const float* __restrict__ Wl, const float* __restrict__ bl,
    const float* __restrict__ Wr, const float* __restrict__ br,
    const float* __restrict__ lng, const float* __restrict__ lnb) {
    __shared__ unsigned As_[128 * LDK];
    __shared__ unsigned Bs_[128 * LDK];
    __shared__ float red_s[128][2][2];
    __shared__ float bias_s[128], lng_s[128], lnb_s[128];

    const int tid = threadIdx.x;
    const int block_m = m_base + blockIdx.x * 128;

    if (tid < 128) {
        bias_s[tid] = bl[tid] + br[tid];
        lng_s[tid] = lng[tid];
        lnb_s[tid] = lnb[tid];
    }

    const int wid = tid >> 5, lane = tid & 31;
    const int wm = wid >> 1, wn = wid & 1;
    const int g = lane >> 2, c = lane & 3;
    const int m_w = 32 * wm, n_w = 64 * wn;

    float d[2][8][4];
#pragma unroll
    for (int mt = 0; mt < 2; mt++)
#pragma unroll
        for (int nt = 0; nt < 8; nt++)
#pragma unroll
            for (int r = 0; r < 4; r++) d[mt][nt][r] = 0.f;

    for (int k0 = 0; k0 < 2 * DD; k0 += 32) {
        const float* Wsrc = (k0 < DD) ? Wl : Wr;
        const int kw0 = k0 & (DD - 1);
#pragma unroll
        for (int i = 0; i < 4; i++) {
            int idx = tid + 256 * i;
            int row = idx >> 3;
            int kq = (idx & 7) * 4;
            int gm = block_m + row;
            float4 av = make_float4(0.f, 0.f, 0.f, 0.f);
            if (gm < NN) {
                int k = k0 + kq;
                if (k < DD) av = *(const float4*)(&g_agg[(size_t)gm * DD + k]);
                else        av = *(const float4*)(hin + (size_t)gm * DD + (k - DD));
            }
            *(uint4*)&As_[row * LDK + kq] =
                make_uint4(f2tf32(av.x), f2tf32(av.y), f2tf32(av.z), f2tf32(av.w));

            float4 wv = *(const float4*)(Wsrc + row * DD + kw0 + kq);
            *(uint4*)&Bs_[row * LDK + kq] =
                make_uint4(f2tf32(wv.x), f2tf32(wv.y), f2tf32(wv.z), f2tf32(wv.w));
        }
        __syncthreads();

#pragma unroll
        for (int ks = 0; ks < 4; ks++) {
            const int kk = ks * 8;
            unsigned a[2][4];
#pragma unroll
            for (int mt = 0; mt < 2; mt++) {
                int mr = m_w + 16 * mt + g;
                a[mt][0] = As_[mr * LDK + kk + c];
                a[mt][1] = As_[(mr + 8) * LDK + kk + c];
                a[mt][2] = As_[mr * LDK + kk + c + 4];
                a[mt][3] = As_[(mr + 8) * LDK + kk + c + 4];
            }
            unsigned bf[8][2];
#pragma unroll
            for (int nt = 0; nt < 8; nt++) {
                int n = n_w + 8 * nt + g;
                bf[nt][0] = Bs_[n * LDK + kk + c];
                bf[nt][1] = Bs_[n * LDK + kk + c + 4];
            }
#pragma unroll
            for (int mt = 0; mt < 2; mt++)
#pragma unroll
                for (int nt = 0; nt < 8; nt++)
                    mma_tf32(d[mt][nt], a[mt], bf[nt]);
        }
        __syncthreads();
    }

#pragma unroll
    for (int mt = 0; mt < 2; mt++) {
        float s0 = 0.f, q0 = 0.f, s1 = 0.f, q1 = 0.f;
#pragma unroll
        for (int nt = 0; nt < 8; nt++) {
            int col = n_w + 8 * nt + 2 * c;
            float b0 = bias_s[col], b1 = bias_s[col + 1];
            float v0 = d[mt][nt][0] + b0, v1 = d[mt][nt][1] + b1;
            float v2 = d[mt][nt][2] + b0, v3 = d[mt][nt][3] + b1;
            d[mt][nt][0] = v0; d[mt][nt][1] = v1;
            d[mt][nt][2] = v2; d[mt][nt][3] = v3;
            s0 += v0 + v1; q0 += v0 * v0 + v1 * v1;
            s1 += v2 + v3; q1 += v2 * v2 + v3 * v3;
        }
#pragma unroll
        for (int off = 1; off <= 2; off <<= 1) {
            s0 += __shfl_xor_sync(0xffffffffu, s0, off);
            q0 += __shfl_xor_sync(0xffffffffu, q0, off);
            s1 += __shfl_xor_sync(0xffffffffu, s1, off);
            q1 += __shfl_xor_sync(0xffffffffu, q1, off);
        }
        if (c == 0) {
            int r0 = m_w + 16 * mt + g;
            red_s[r0][wn][0] = s0; red_s[r0][wn][1] = q0;
            red_s[r0 + 8][wn][0] = s1; red_s[r0 + 8][wn][1] = q1;
        }
    }
    __syncthreads();

#pragma unroll
    for (int mt = 0; mt < 2; mt++) {
        int r0 = m_w + 16 * mt + g;
        int r1 = r0 + 8;
        float sum0 = red_s[r0][0][0] + red_s[r0][1][0];
        float ssq0 = red_s[r0][0][1] + red_s[r0][1][1];
        float sum1 = red_s[r1][0][0] + red_s[r1][1][0];
        float ssq1 = red_s[r1][0][1] + red_s[r1][1][1];
        float mu0 = sum0 * (1.0f / DD);
        float rs0 = rsqrtf(ssq0 * (1.0f / DD) - mu0 * mu0 + LN_EPS);
        float mu1 = sum1 * (1.0f / DD);
        float rs1 = rsqrtf(ssq1 * (1.0f / DD) - mu1 * mu1 + LN_EPS);
        int gm0 = block_m + r0, gm1 = block_m + r1;
#pragma unroll
        for (int nt = 0; nt < 8; nt++) {
            int col = n_w + 8 * nt + 2 * c;
            float gg0 = lng_s[col], gg1 = lng_s[col + 1];
            float bb0 = lnb_s[col], bb1 = lnb_s[col + 1];
            if (gm0 < NN) {
                float y0 = (d[mt][nt][0] - mu0) * rs0 * gg0 + bb0;
                float y1 = (d[mt][nt][1] - mu0) * rs0 * gg1 + bb1;
                y0 = y0 / (1.f + __expf(-y0));
                y1 = y1 / (1.f + __expf(-y1));
                *(float2*)&hout[(size_t)gm0 * DD + col] = make_float2(y0, y1);
            }
            if (gm1 < NN) {
                float y2 = (d[mt][nt][2] - mu1) * rs1 * gg0 + bb0;
                float y3 = (d[mt][nt][3] - mu1) * rs1 * gg1 + bb1;
                y2 = y2 / (1.f + __expf(-y2));
                y3 = y3 / (1.f + __expf(-y3));
                *(float2*)&hout[(size_t)gm1 * DD + col] = make_float2(y2, y3);
            }
        }
    }
}

// ---- fused MLP head (chunked): out = relu(hin @ W1^T + b1) @ w2 + b2 ----
__global__ __launch_bounds__(256, 2) void k_mlp_fused(const float* __restrict__ hin,
                                                      int m_base,
                                                      const float* __restrict__ W1,
                                                      const float* __restrict__ b1,
                                                      const float* __restrict__ w2,
                                                      const float* __restrict__ b2,
                                                      float* __restrict__ out) {
    __shared__ unsigned As_[128 * LDK];
    __shared__ unsigned Bs_[128 * LDK];
    __shared__ float red_s[128][2];
    __shared__ float bias_s[128], w2_s[128];

    const int tid = threadIdx.x;
    const int block_m = m_base + blockIdx.x * 128;
    if (tid < 128) {
        bias_s[tid] = b1[tid];
        w2_s[tid] = w2[tid];
    }

    const int wid = tid >> 5, lane = tid & 31;
    const int wm = wid >> 1, wn = wid & 1;
    const int g = lane >> 2, c = lane & 3;
    const int m_w = 32 * wm, n_w = 64 * wn;

    float d[2][8][4];
#pragma unroll
    for (int mt = 0; mt < 2; mt++)
#pragma unroll
        for (int nt = 0; nt < 8; nt++)
#pragma unroll
            for (int r = 0; r < 4; r++) d[mt][nt][r] = 0.f;

    for (int k0 = 0; k0 < DD; k0 += 32) {
#pragma unroll
        for (int i = 0; i < 4; i++) {
            int idx = tid + 256 * i;
            int row = idx >> 3;
            int kq = (idx & 7) * 4;
            int gm = block_m + row;
            float4 av = make_float4(0.f, 0.f, 0.f, 0.f);
            if (gm < NN) av = *(const float4*)(hin + (size_t)gm * DD + k0 + kq);
            *(uint4*)&As_[row * LDK + kq] =
                make_uint4(f2tf32(av.x), f2tf32(av.y), f2tf32(av.z), f2tf32(av.w));

            float4 wv = *(const float4*)(W1 + row * DD + k0 + kq);
            *(uint4*)&Bs_[row * LDK + kq] =
                make_uint4(f2tf32(wv.x), f2tf32(wv.y), f2tf32(wv.z), f2tf32(wv.w));
        }
        __syncthreads();

#pragma unroll
        for (int ks = 0; ks < 4; ks++) {
            const int kk = ks * 8;
            unsigned a[2][4];
#pragma unroll
            for (int mt = 0; mt < 2; mt++) {
                int mr = m_w + 16 * mt + g;
                a[mt][0] = As_[mr * LDK + kk + c];
                a[mt][1] = As_[(mr + 8) * LDK + kk + c];
                a[mt][2] = As_[mr * LDK + kk + c + 4];
                a[mt][3] = As_[(mr + 8) * LDK + kk + c + 4];
            }
            unsigned bf[8][2];
#pragma unroll
            for (int nt = 0; nt < 8; nt++) {
                int n = n_w + 8 * nt + g;
                bf[nt][0] = Bs_[n * LDK + kk + c];
                bf[nt][1] = Bs_[n * LDK + kk + c + 4];
            }
#pragma unroll
            for (int mt = 0; mt < 2; mt++)
#pragma unroll
                for (int nt = 0; nt < 8; nt++)
                    mma_tf32(d[mt][nt], a[mt], bf[nt]);
        }
        __syncthreads();
    }

#pragma unroll
    for (int mt = 0; mt < 2; mt++) {
        float p0 = 0.f, p1 = 0.f;
#pragma unroll
        for (int nt = 0; nt < 8; nt++) {
            int col = n_w + 8 * nt + 2 * c;
            float b0 = bias_s[col], b1v = bias_s[col + 1];
            float w0 = w2_s[col], w1 = w2_s[col + 1];
            p0 += fmaxf(d[mt][nt][0] + b0, 0.f) * w0
                + fmaxf(d[mt][nt][1] + b1v, 0.f) * w1;
            p1 += fmaxf(d[mt][nt][2] + b0, 0.f) * w0
                + fmaxf(d[mt][nt][3] + b1v, 0.f) * w1;
        }
#pragma unroll
        for (int off = 1; off <= 2; off <<= 1) {
            p0 += __shfl_xor_sync(0xffffffffu, p0, off);
            p1 += __shfl_xor_sync(0xffffffffu, p1, off);
        }
        if (c == 0) {
            int r0 = m_w + 16 * mt + g;
            red_s[r0][wn] = p0;
            red_s[r0 + 8][wn] = p1;
        }
    }
    __syncthreads();
    if (tid < 128) {
        int gm = block_m + tid;
        if (gm < NN) out[gm] = red_s[tid][0] + red_s[tid][1] + b2[0];
    }
}

// ---------------- launch ----------------
extern "C" void kernel_launch(void* const* d_in, const int* in_sizes, int n_in,
                              void* d_out, int out_size) {
    const float* x = (const float*)d_in[0];
    const void* ei = d_in[1];
    const float* lin_l_w = (const float*)d_in[2];
    const float* lin_l_b = (const float*)d_in[3];
    const float* lin_r_w = (const float*)d_in[4];
    const float* lin_r_b = (const float*)d_in[5];
    const float* ln_g = (const float*)d_in[6];
    const float* ln_b = (const float*)d_in[7];
    const float* mlp_w1 = (const float*)d_in[8];
    const float* mlp_b1 = (const float*)d_in[9];
    const float* mlp_w2 = (const float*)d_in[10];
    const float* mlp_b2 = (const float*)d_in[11];
    float* out = (float*)d_out;

    float *p_h, *p_h2;
    cudaGetSymbolAddress((void**)&p_h, g_h);
    cudaGetSymbolAddress((void**)&p_h2, g_h2);

    // one-time host resources (no device memory; capture-legal fork/join)
    static cudaStream_t s2 = nullptr;
    static cudaEvent_t ev[12];
    if (!s2) {
        cudaStreamCreateWithFlags(&s2, cudaStreamNonBlocking);
        for (int i = 0; i < 12; i++)
            cudaEventCreateWithFlags(&ev[i], cudaEventDisableTiming);
    }

    const int T = 256;
    static const int bounds[NCHUNK + 1] = {0, 25088, 50176, 75264, NN};

    // ---- dtype detect + CSR build (default stream) ----
    k_init<<<(NN + T - 1) / T, T>>>((const unsigned*)ei);
    k_deg_count<<<(EE + T - 1) / T, T>>>(ei);
    k_scan_block<<<NB, SCAN_BLK>>>();
    k_scan_finalize<<<(NN + T - 1) / T, T>>>();
    k_fill<<<(EE + T - 1) / T, T>>>(ei);

    // ---- layer 0: agg chunks on default, GEMM chunks on s2 ----
    for (int c = 0; c < NCHUNK; c++) {
        int base = bounds[c], cnt = bounds[c + 1] - base;
        k_aggregate<<<(cnt * 32 + T - 1) / T, T>>>(x, base, cnt);
        cudaEventRecord(ev[c], 0);
        cudaStreamWaitEvent(s2, ev[c], 0);
        k_layer_tc<<<(cnt + 127) / 128, T, 0, s2>>>(
            x, p_h, base, lin_l_w, lin_l_b, lin_r_w, lin_r_b, ln_g, ln_b);
    }
    cudaEventRecord(ev[4], s2);
    cudaStreamWaitEvent(0, ev[4], 0);   // layer-1 gather needs ALL of g_h

    // ---- layer 1 + MLP: agg on default; GEMM->MLP chained per chunk on s2 ----
    for (int c = 0; c < NCHUNK; c++) {
        int base = bounds[c], cnt = bounds[c + 1] - base;
        k_aggregate<<<(cnt * 32 + T - 1) / T, T>>>(p_h, base, cnt);
        cudaEventRecord(ev[5 + c], 0);
        cudaStreamWaitEvent(s2, ev[5 + c], 0);
        k_layer_tc<<<(cnt + 127) / 128, T, 0, s2>>>(
            p_h, p_h2, base,
            lin_l_w + DD * DD, lin_l_b + DD,
            lin_r_w + DD * DD, lin_r_b + DD,
            ln_g + DD, ln_b + DD);
        k_mlp_fused<<<(cnt + 127) / 128, T, 0, s2>>>(
            p_h2, base, mlp_w1, mlp_b1, mlp_w2, mlp_b2, out);
    }
    cudaEventRecord(ev[9], s2);
    cudaStreamWaitEvent(0, ev[9], 0);   // join back into origin stream
}

// round 11
// speedup vs baseline: 1.2510x; 1.1011x over previous
#include <cuda_runtime.h>
#include <cuda_bf16.h>
#include <cstdint>

#define NN 100000
#define EE 1600000
#define DD 128
#define LN_EPS 1e-5f
#define SCAN_BLK 1024
#define NB ((NN + SCAN_BLK - 1) / SCAN_BLK)   // 98

// ---------------- scratch (no allocs allowed) ----------------
__device__ float g_h[(size_t)NN * DD];    // layer-0 output (tf32-rounded bits)
__device__ float g_h2[(size_t)NN * DD];   // layer-1 output (tf32-rounded bits)
__device__ float g_agg[(size_t)NN * DD];  // mean aggregates (tf32-rounded bits)
__device__ unsigned g_wt[5 * DD * DD];    // tf32 weights: wl0,wr0,wl1,wr1,w1
__device__ int   g_rowptr[NN + 1];
__device__ int   g_cursor[NN];
__device__ int   g_col[EE];
__device__ int   g_blocksum[128];
__device__ int   g_is64;

// ---------------- tf32 helpers ----------------
__device__ __forceinline__ unsigned f2tf32(float f) {
    unsigned u;
    asm("cvt.rna.tf32.f32 %0, %1;" : "=r"(u) : "f"(f));
    return u;
}

__device__ __forceinline__ void mma_tf32(float* d, const unsigned* a,
                                         const unsigned* b) {
    asm volatile(
        "mma.sync.aligned.m16n8k8.row.col.f32.tf32.tf32.f32 "
        "{%0,%1,%2,%3}, {%4,%5,%6,%7}, {%8,%9}, {%0,%1,%2,%3};"
        : "+f"(d[0]), "+f"(d[1]), "+f"(d[2]), "+f"(d[3])
        : "r"(a[0]), "r"(a[1]), "r"(a[2]), "r"(a[3]), "r"(b[0]), "r"(b[1]));
}

// ---------------- init: zero cursor; block 0 detects dtype ----------------
__global__ __launch_bounds__(256) void k_init(const unsigned* __restrict__ w) {
    int i = blockIdx.x * blockDim.x + threadIdx.x;
    if (i < NN) g_cursor[i] = 0;
    if (blockIdx.x == 0) {
        __shared__ unsigned s[256];
        int tid = threadIdx.x;
        unsigned v = 0;
#pragma unroll
        for (int k = 0; k < 8; k++) v |= w[2 * (tid + 256 * k) + 1];
        s[tid] = v;
        __syncthreads();
        for (int off = 128; off > 0; off >>= 1) {
            if (tid < off) s[tid] |= s[tid + off];
            __syncthreads();
        }
        if (tid == 0) g_is64 = (s[0] == 0u) ? 1 : 0;
    }
}

// pre-convert the 5 weight matrices to tf32 bits
__global__ __launch_bounds__(256) void k_prep_w(const float* __restrict__ lw,
                                                const float* __restrict__ rw,
                                                const float* __restrict__ w1) {
    int i = blockIdx.x * blockDim.x + threadIdx.x;
    if (i >= 5 * DD * DD) return;
    int m = i >> 14, r = i & (DD * DD - 1);
    float v;
    if (m == 0)      v = lw[r];
    else if (m == 1) v = rw[r];
    else if (m == 2) v = lw[DD * DD + r];
    else if (m == 3) v = rw[DD * DD + r];
    else             v = w1[r];
    g_wt[i] = f2tf32(v);
}

__device__ __forceinline__ int edge_at(const void* ei, size_t idx) {
    int v;
    if (g_is64) v = (int)((const long long*)ei)[idx];
    else        v = ((const int*)ei)[idx];
    v = (v < 0) ? 0 : (v >= NN ? NN - 1 : v);
    return v;
}

// ---------------- CSR build ----------------
__global__ void k_deg_count(const void* __restrict__ ei) {
    int e = blockIdx.x * blockDim.x + threadIdx.x;
    if (e < EE) atomicAdd(&g_cursor[edge_at(ei, (size_t)EE + e)], 1);
}

__global__ __launch_bounds__(SCAN_BLK) void k_scan_block() {
    __shared__ int s[SCAN_BLK];
    int tid = threadIdx.x;
    int i = blockIdx.x * SCAN_BLK + tid;
    int v = (i < NN) ? g_cursor[i] : 0;
    s[tid] = v;
    __syncthreads();
#pragma unroll
    for (int off = 1; off < SCAN_BLK; off <<= 1) {
        int t = (tid >= off) ? s[tid - off] : 0;
        __syncthreads();
        s[tid] += t;
        __syncthreads();
    }
    if (i < NN) g_rowptr[i + 1] = s[tid];
    if (tid == SCAN_BLK - 1) g_blocksum[blockIdx.x] = s[tid];
}

__global__ __launch_bounds__(256) void k_scan_finalize() {
    __shared__ int pre_s;
    int i = blockIdx.x * 256 + threadIdx.x;
    if (threadIdx.x == 0) {
        int b = blockIdx.x >> 2;
        int run = 0;
        for (int j = 0; j < b; j++) run += g_blocksum[j];
        pre_s = run;
    }
    __syncthreads();
    if (i >= NN) return;
    g_rowptr[i + 1] += pre_s;
    if (i == 0) g_rowptr[0] = 0;
    g_cursor[i] = 0;
}

__global__ void k_fill(const void* __restrict__ ei) {
    int e = blockIdx.x * blockDim.x + threadIdx.x;
    if (e >= EE) return;
    int dst = edge_at(ei, (size_t)EE + e);
    int src = edge_at(ei, (size_t)e);
    int pos = g_rowptr[dst] + atomicAdd(&g_cursor[dst], 1);
    g_col[pos] = src;
}

// ---------------- pull-mode mean aggregation (warp per node) ---------------
// output rounded to tf32 bits so the GEMM can skip cvt
__global__ __launch_bounds__(256) void k_aggregate(const float* __restrict__ xin,
                                                   int use_gh) {
    int warp = (blockIdx.x * blockDim.x + threadIdx.x) >> 5;
    int lane = threadIdx.x & 31;
    if (warp >= NN) return;
    const float* hin = use_gh ? g_h : xin;
    int start = g_rowptr[warp];
    int end = g_rowptr[warp + 1];
    float4 a0 = make_float4(0.f, 0.f, 0.f, 0.f);
    float4 a1 = make_float4(0.f, 0.f, 0.f, 0.f);
    int j = start;
    for (; j + 4 <= end; j += 4) {
        int s0 = g_col[j], s1 = g_col[j + 1], s2 = g_col[j + 2], s3 = g_col[j + 3];
        float4 v0 = ((const float4*)(hin + (size_t)s0 * DD))[lane];
        float4 v1 = ((const float4*)(hin + (size_t)s1 * DD))[lane];
        float4 v2 = ((const float4*)(hin + (size_t)s2 * DD))[lane];
        float4 v3 = ((const float4*)(hin + (size_t)s3 * DD))[lane];
        a0.x += v0.x; a0.y += v0.y; a0.z += v0.z; a0.w += v0.w;
        a1.x += v1.x; a1.y += v1.y; a1.z += v1.z; a1.w += v1.w;
        a0.x += v2.x; a0.y += v2.y; a0.z += v2.z; a0.w += v2.w;
        a1.x += v3.x; a1.y += v3.y; a1.z += v3.z; a1.w += v3.w;
    }
    for (; j < end; j++) {
        float4 v = ((const float4*)(hin + (size_t)g_col[j] * DD))[lane];
        a0.x += v.x; a0.y += v.y; a0.z += v.z; a0.w += v.w;
    }
    float inv = (end > start) ? (1.0f / (float)(end - start)) : 0.0f;
    uint4 r;
    r.x = f2tf32((a0.x + a1.x) * inv);
    r.y = f2tf32((a0.y + a1.y) * inv);
    r.z = f2tf32((a0.z + a1.z) * inv);
    r.w = f2tf32((a0.w + a1.w) * inv);
    ((uint4*)(g_agg + (size_t)warp * DD))[lane] = r;
}

#define LDK 36

// ---- fused SAGE layer: hout = SiLU(LN([g_agg | hin] @ [Wl|Wr]^T + b)) ----
// CVTA: convert A-halves to tf32 at smem store (needed only when hin = raw x).
// Weights come pre-converted from g_wt (wsel = matrix pair index).
template <bool CVTA>
__global__ __launch_bounds__(256, 2) void k_layer_tc(
    const float* __restrict__ hin, float* __restrict__ hout, int wsel,
    const float* __restrict__ bl, const float* __restrict__ br,
    const float* __restrict__ lng, const float* __restrict__ lnb) {
    __shared__ unsigned As_[128 * LDK];
    __shared__ unsigned Bs_[128 * LDK];
    __shared__ float red_s[128][2][2];
    __shared__ float bias_s[128], lng_s[128], lnb_s[128];

    const int tid = threadIdx.x;
    const int block_m = blockIdx.x * 128;
    const unsigned* Wl_t = g_wt + (size_t)wsel * DD * DD;
    const unsigned* Wr_t = Wl_t + DD * DD;

    if (tid < 128) {
        bias_s[tid] = bl[tid] + br[tid];
        lng_s[tid] = lng[tid];
        lnb_s[tid] = lnb[tid];
    }

    const int wid = tid >> 5, lane = tid & 31;
    const int wm = wid >> 1, wn = wid & 1;
    const int g = lane >> 2, c = lane & 3;
    const int m_w = 32 * wm, n_w = 64 * wn;

    float d[2][8][4];
#pragma unroll
    for (int mt = 0; mt < 2; mt++)
#pragma unroll
        for (int nt = 0; nt < 8; nt++)
#pragma unroll
            for (int r = 0; r < 4; r++) d[mt][nt][r] = 0.f;

    for (int k0 = 0; k0 < 2 * DD; k0 += 32) {
        const unsigned* Wsrc = (k0 < DD) ? Wl_t : Wr_t;
        const int kw0 = k0 & (DD - 1);
#pragma unroll
        for (int i = 0; i < 4; i++) {
            int idx = tid + 256 * i;
            int row = idx >> 3;
            int kq = (idx & 7) * 4;
            int gm = block_m + row;
            float4 av = make_float4(0.f, 0.f, 0.f, 0.f);
            if (gm < NN) {
                int k = k0 + kq;
                if (k < DD) av = *(const float4*)(&g_agg[(size_t)gm * DD + k]);
                else        av = *(const float4*)(hin + (size_t)gm * DD + (k - DD));
            }
            if (CVTA) {
                *(uint4*)&As_[row * LDK + kq] =
                    make_uint4(f2tf32(av.x), f2tf32(av.y), f2tf32(av.z), f2tf32(av.w));
            } else {
                *(uint4*)&As_[row * LDK + kq] = *(uint4*)&av;
            }
            *(uint4*)&Bs_[row * LDK + kq] =
                *(const uint4*)(Wsrc + row * DD + kw0 + kq);
        }
        __syncthreads();

#pragma unroll
        for (int ks = 0; ks < 4; ks++) {
            const int kk = ks * 8;
            unsigned a[2][4];
#pragma unroll
            for (int mt = 0; mt < 2; mt++) {
                int mr = m_w + 16 * mt + g;
                a[mt][0] = As_[mr * LDK + kk + c];
                a[mt][1] = As_[(mr + 8) * LDK + kk + c];
                a[mt][2] = As_[mr * LDK + kk + c + 4];
                a[mt][3] = As_[(mr + 8) * LDK + kk + c + 4];
            }
            unsigned bf[8][2];
#pragma unroll
            for (int nt = 0; nt < 8; nt++) {
                int n = n_w + 8 * nt + g;
                bf[nt][0] = Bs_[n * LDK + kk + c];
                bf[nt][1] = Bs_[n * LDK + kk + c + 4];
            }
#pragma unroll
            for (int mt = 0; mt < 2; mt++)
#pragma unroll
                for (int nt = 0; nt < 8; nt++)
                    mma_tf32(d[mt][nt], a[mt], bf[nt]);
        }
        __syncthreads();
    }

    // ---- epilogue: bias, LN, SiLU, tf32-round, store ----
#pragma unroll
    for (int mt = 0; mt < 2; mt++) {
        float s0 = 0.f, q0 = 0.f, s1 = 0.f, q1 = 0.f;
#pragma unroll
        for (int nt = 0; nt < 8; nt++) {
            int col = n_w + 8 * nt + 2 * c;
            float b0 = bias_s[col], b1 = bias_s[col + 1];
            float v0 = d[mt][nt][0] + b0, v1 = d[mt][nt][1] + b1;
            float v2 = d[mt][nt][2] + b0, v3 = d[mt][nt][3] + b1;
            d[mt][nt][0] = v0; d[mt][nt][1] = v1;
            d[mt][nt][2] = v2; d[mt][nt][3] = v3;
            s0 += v0 + v1; q0 += v0 * v0 + v1 * v1;
            s1 += v2 + v3; q1 += v2 * v2 + v3 * v3;
        }
#pragma unroll
        for (int off = 1; off <= 2; off <<= 1) {
            s0 += __shfl_xor_sync(0xffffffffu, s0, off);
            q0 += __shfl_xor_sync(0xffffffffu, q0, off);
            s1 += __shfl_xor_sync(0xffffffffu, s1, off);
            q1 += __shfl_xor_sync(0xffffffffu, q1, off);
        }
        if (c == 0) {
            int r0 = m_w + 16 * mt + g;
            red_s[r0][wn][0] = s0; red_s[r0][wn][1] = q0;
            red_s[r0 + 8][wn][0] = s1; red_s[r0 + 8][wn][1] = q1;
        }
    }
    __syncthreads();

#pragma unroll
    for (int mt = 0; mt < 2; mt++) {
        int r0 = m_w + 16 * mt + g;
        int r1 = r0 + 8;
        float sum0 = red_s[r0][0][0] + red_s[r0][1][0];
        float ssq0 = red_s[r0][0][1] + red_s[r0][1][1];
        float sum1 = red_s[r1][0][0] + red_s[r1][1][0];
        float ssq1 = red_s[r1][0][1] + red_s[r1][1][1];
        float mu0 = sum0 * (1.0f / DD);
        float rs0 = rsqrtf(ssq0 * (1.0f / DD) - mu0 * mu0 + LN_EPS);
        float mu1 = sum1 * (1.0f / DD);
        float rs1 = rsqrtf(ssq1 * (1.0f / DD) - mu1 * mu1 + LN_EPS);
        int gm0 = block_m + r0, gm1 = block_m + r1;
#pragma unroll
        for (int nt = 0; nt < 8; nt++) {
            int col = n_w + 8 * nt + 2 * c;
            float gg0 = lng_s[col], gg1 = lng_s[col + 1];
            float bb0 = lnb_s[col], bb1 = lnb_s[col + 1];
            if (gm0 < NN) {
                float y0 = (d[mt][nt][0] - mu0) * rs0 * gg0 + bb0;
                float y1 = (d[mt][nt][1] - mu0) * rs0 * gg1 + bb1;
                y0 = y0 / (1.f + __expf(-y0));
                y1 = y1 / (1.f + __expf(-y1));
                uint2 o = make_uint2(f2tf32(y0), f2tf32(y1));
                *(uint2*)&hout[(size_t)gm0 * DD + col] = o;
            }
            if (gm1 < NN) {
                float y2 = (d[mt][nt][2] - mu1) * rs1 * gg0 + bb0;
                float y3 = (d[mt][nt][3] - mu1) * rs1 * gg1 + bb1;
                y2 = y2 / (1.f + __expf(-y2));
                y3 = y3 / (1.f + __expf(-y3));
                uint2 o = make_uint2(f2tf32(y2), f2tf32(y3));
                *(uint2*)&hout[(size_t)gm1 * DD + col] = o;
            }
        }
    }
}

// ---- fused MLP head: out = relu(hin @ W1^T + b1) @ w2 + b2 ----
// hin pre-rounded to tf32 bits; W1 pre-converted in g_wt[4].
__global__ __launch_bounds__(256, 2) void k_mlp_fused(const float* __restrict__ hin,
                                                      const float* __restrict__ b1,
                                                      const float* __restrict__ w2,
                                                      const float* __restrict__ b2,
                                                      float* __restrict__ out) {
    __shared__ unsigned As_[128 * LDK];
    __shared__ unsigned Bs_[128 * LDK];
    __shared__ float red_s[128][2];
    __shared__ float bias_s[128], w2_s[128];

    const int tid = threadIdx.x;
    const int block_m = blockIdx.x * 128;
    const unsigned* W1_t = g_wt + (size_t)4 * DD * DD;
    if (tid < 128) {
        bias_s[tid] = b1[tid];
        w2_s[tid] = w2[tid];
    }

    const int wid = tid >> 5, lane = tid & 31;
    const int wm = wid >> 1, wn = wid & 1;
    const int g = lane >> 2, c = lane & 3;
    const int m_w = 32 * wm, n_w = 64 * wn;

    float d[2][8][4];
#pragma unroll
    for (int mt = 0; mt < 2; mt++)
#pragma unroll
        for (int nt = 0; nt < 8; nt++)
#pragma unroll
            for (int r = 0; r < 4; r++) d[mt][nt][r] = 0.f;

    for (int k0 = 0; k0 < DD; k0 += 32) {
#pragma unroll
        for (int i = 0; i < 4; i++) {
            int idx = tid + 256 * i;
            int row = idx >> 3;
            int kq = (idx & 7) * 4;
            int gm = block_m + row;
            uint4 av = make_uint4(0u, 0u, 0u, 0u);
            if (gm < NN) av = *(const uint4*)(hin + (size_t)gm * DD + k0 + kq);
            *(uint4*)&As_[row * LDK + kq] = av;
            *(uint4*)&Bs_[row * LDK + kq] =
                *(const uint4*)(W1_t + row * DD + k0 + kq);
        }
        __syncthreads();

#pragma unroll
        for (int ks = 0; ks < 4; ks++) {
            const int kk = ks * 8;
            unsigned a[2][4];
#pragma unroll
            for (int mt = 0; mt < 2; mt++) {
                int mr = m_w + 16 * mt + g;
                a[mt][0] = As_[mr * LDK + kk + c];
                a[mt][1] = As_[(mr + 8) * LDK + kk + c];
                a[mt][2] = As_[mr * LDK + kk + c + 4];
                a[mt][3] = As_[(mr + 8) * LDK + kk + c + 4];
            }
            unsigned bf[8][2];
#pragma unroll
            for (int nt = 0; nt < 8; nt++) {
                int n = n_w + 8 * nt + g;
                bf[nt][0] = Bs_[n * LDK + kk + c];
                bf[nt][1] = Bs_[n * LDK + kk + c + 4];
            }
#pragma unroll
            for (int mt = 0; mt < 2; mt++)
#pragma unroll
                for (int nt = 0; nt < 8; nt++)
                    mma_tf32(d[mt][nt], a[mt], bf[nt]);
        }
        __syncthreads();
    }

#pragma unroll
    for (int mt = 0; mt < 2; mt++) {
        float p0 = 0.f, p1 = 0.f;
#pragma unroll
        for (int nt = 0; nt < 8; nt++) {
            int col = n_w + 8 * nt + 2 * c;
            float b0 = bias_s[col], b1v = bias_s[col + 1];
            float w0 = w2_s[col], w1 = w2_s[col + 1];
            p0 += fmaxf(d[mt][nt][0] + b0, 0.f) * w0
                + fmaxf(d[mt][nt][1] + b1v, 0.f) * w1;
            p1 += fmaxf(d[mt][nt][2] + b0, 0.f) * w0
                + fmaxf(d[mt][nt][3] + b1v, 0.f) * w1;
        }
#pragma unroll
        for (int off = 1; off <= 2; off <<= 1) {
            p0 += __shfl_xor_sync(0xffffffffu, p0, off);
            p1 += __shfl_xor_sync(0xffffffffu, p1, off);
        }
        if (c == 0) {
            int r0 = m_w + 16 * mt + g;
            red_s[r0][wn] = p0;
            red_s[r0 + 8][wn] = p1;
        }
    }
    __syncthreads();
    if (tid < 128) {
        int gm = block_m + tid;
        if (gm < NN) out[gm] = red_s[tid][0] + red_s[tid][1] + b2[0];
    }
}

// ---------------- launch ----------------
extern "C" void kernel_launch(void* const* d_in, const int* in_sizes, int n_in,
                              void* d_out, int out_size) {
    const float* x = (const float*)d_in[0];
    const void* ei = d_in[1];
    const float* lin_l_w = (const float*)d_in[2];
    const float* lin_l_b = (const float*)d_in[3];
    const float* lin_r_w = (const float*)d_in[4];
    const float* lin_r_b = (const float*)d_in[5];
    const float* ln_g = (const float*)d_in[6];
    const float* ln_b = (const float*)d_in[7];
    const float* mlp_w1 = (const float*)d_in[8];
    const float* mlp_b1 = (const float*)d_in[9];
    const float* mlp_w2 = (const float*)d_in[10];
    const float* mlp_b2 = (const float*)d_in[11];
    float* out = (float*)d_out;

    float *p_h, *p_h2;
    cudaGetSymbolAddress((void**)&p_h, g_h);
    cudaGetSymbolAddress((void**)&p_h2, g_h2);

    const int T = 256;
    const int gemm_grid = (NN + 127) / 128;          // 782
    const int node_warp_grid = (NN * 32 + T - 1) / T;

    // ---- dtype detect + weight prep + CSR build ----
    k_init<<<(NN + T - 1) / T, T>>>((const unsigned*)ei);
    k_prep_w<<<(5 * DD * DD + T - 1) / T, T>>>(lin_l_w, lin_r_w, mlp_w1);
    k_deg_count<<<(EE + T - 1) / T, T>>>(ei);
    k_scan_block<<<NB, SCAN_BLK>>>();
    k_scan_finalize<<<(NN + T - 1) / T, T>>>();
    k_fill<<<(EE + T - 1) / T, T>>>(ei);

    // ---- layer 0: gather x -> GEMM -> g_h (A needs cvt: x is raw fp32) ----
    k_aggregate<<<node_warp_grid, T>>>(x, 0);
    k_layer_tc<true><<<gemm_grid, T>>>(x, p_h, 0,
                                       lin_l_b, lin_r_b, ln_g, ln_b);

    // ---- layer 1: gather g_h -> GEMM -> g_h2 (all inputs pre-rounded) ----
    k_aggregate<<<node_warp_grid, T>>>(x, 1);
    k_layer_tc<false><<<gemm_grid, T>>>(p_h, p_h2, 2,
                                        lin_l_b + DD, lin_r_b + DD,
                                        ln_g + DD, ln_b + DD);

    // ---- fused MLP head ----
    k_mlp_fused<<<gemm_grid, T>>>(p_h2, mlp_b1, mlp_w2, mlp_b2, out);
}